// round 6
// baseline (speedup 1.0000x reference)
#include <cuda_runtime.h>
#include <math.h>

#define Bc 8
#define Sc 512
#define Nc (Sc*Sc)
#define NBs 128
#define TPBs 256
#define CPBs (Nc/NBs)
#define ITERS 20
#define EPSF 1e-6f
#define INVH 511.0f
#define HF (1.0f/511.0f)
#define HH (HF*HF)
#define GAMMA_F 10.0f
#define THRESH_F 0.5f

// persistent kernel config
#define PB 256
#define PT 512
#define BPB 32
#define ROWS 16

// ---- scratch ----
__device__ float g_cxs[Bc*(Sc-1)*Sc];
__device__ float g_cys[Bc*Sc*(Sc-1)];
__device__ float g_lap[Bc*Nc];
__device__ float g_rho[Bc*Nc];
__device__ float g_P[Bc*Nc];
__device__ float g_Q[Bc*Nc];
__device__ float g_BB[Bc*Nc];
__device__ float g_BNX[Bc*Nc];
__device__ float g_BNY[Bc*Nc];
__device__ float g_RB[Nc];
__device__ float g_r[Bc*Nc];            // full r field (only edge rows re-written during CG)
__device__ float g_part[Bc*BPB];
__device__ unsigned g_cnt[Bc];
__device__ unsigned long long g_pub[Bc];

// =====================================================================
// S1
// =====================================================================
__global__ void s1_kernel(const float* __restrict__ coeff,
                          const float* __restrict__ u,
                          const float* __restrict__ beta) {
    int b = blockIdx.y;
    size_t off = (size_t)b * Nc;
    const float* C = coeff + off;
    const float* U = u + off;
    const float4* B4 = (const float4*)beta + off;
    int base = blockIdx.x * CPBs;

    for (int t = threadIdx.x; t < CPBs; t += TPBs) {
        int idx = base + t;
        int i = idx >> 9;
        int j = idx & (Sc - 1);
        float c = C[idx];

        if (i < Sc - 1) {
            float cn = C[idx + Sc];
            g_cxs[(size_t)b*(Sc-1)*Sc + idx] = (2.f*c*cn / (c + cn + EPSF)) * (INVH*INVH);
        }
        if (j < Sc - 1) {
            float ce = C[idx + 1];
            g_cys[(size_t)b*Sc*(Sc-1) + (size_t)i*(Sc-1) + j] = (2.f*c*ce / (c + ce + EPSF)) * (INVH*INVH);
        }

        float lap = 0.f;
        if (i > 0 && i < Sc-1 && j > 0 && j < Sc-1) {
            float uc = U[idx];
            lap = ((U[idx+Sc]-uc)*INVH - (uc-U[idx-Sc])*INVH)*INVH
                + ((U[idx+1 ]-uc)*INVH - (uc-U[idx-1 ])*INVH)*INVH;
        }
        g_lap[off + idx] = lap;

        float lc = logf(fmaxf(c, EPSF));
        float glx, gly;
        if (i == 0)          glx = (logf(fmaxf(C[idx+Sc],EPSF)) - lc) * INVH;
        else if (i == Sc-1)  glx = (lc - logf(fmaxf(C[idx-Sc],EPSF))) * INVH;
        else                 glx = (logf(fmaxf(C[idx+Sc],EPSF)) - logf(fmaxf(C[idx-Sc],EPSF))) * (0.5f*INVH);
        if (j == 0)          gly = (logf(fmaxf(C[idx+1],EPSF)) - lc) * INVH;
        else if (j == Sc-1)  gly = (lc - logf(fmaxf(C[idx-1],EPSF))) * INVH;
        else                 gly = (logf(fmaxf(C[idx+1],EPSF)) - logf(fmaxf(C[idx-1],EPSF))) * (0.5f*INVH);

        float eta = sqrtf(glx*glx + gly*gly + EPSF);
        float rho = 1.f / (1.f + expf(-GAMMA_F * (eta - THRESH_F)));
        float nhx = glx / eta, nhy = gly / eta;

        float4 bv = B4[idx];
        g_rho[off+idx] = rho;
        g_P[off+idx]   = bv.y*nhx - bv.z*nhy;
        g_Q[off+idx]   = bv.y*nhy + bv.z*nhx;
        g_BB[off+idx]  = bv.x;

        double dl = 1.0 / 511.0;
        double xx = (i == Sc-1) ? 1.0 : (double)i * dl;
        double yy = (j == Sc-1) ? 1.0 : (double)j * dl;
        double a0 = xx, a1 = 1.0 - xx, a2 = yy, a3 = 1.0 - yy;
        double best = a0; int k = 0;
        if (a1 < best) { best = a1; k = 1; }
        if (a2 < best) { best = a2; k = 2; }
        if (a3 < best) { best = a3; k = 3; }
        float bnx = (k == 0) ? -1.f : ((k == 1) ? 1.f : 0.f);
        float bny = (k == 2) ? -1.f : ((k == 3) ? 1.f : 0.f);
        g_BNX[off+idx] = bv.w * bnx;
        g_BNY[off+idx] = bv.w * bny;
        if (b == 0) {
            float dd = (float)best;
            g_RB[idx] = expf(-(dd*dd) / (0.15f*0.15f));
        }
    }
}

// =====================================================================
// S2: rhs -> g_r
// =====================================================================
__device__ __forceinline__ float fluxX(const float* C, const float* U, const float* LAP,
                                       const float* RHO, const float* PP, const float* BB,
                                       const float* BNX, int a) {
    int b2 = a + Sc;
    float ca = C[a], cb = C[b2];
    float cxf = 2.f*ca*cb / (ca + cb + EPSF);
    float gux = (U[b2] - U[a]) * INVH;
    float lgx = (LAP[b2] - LAP[a]) * INVH;
    return 0.5f*(BB[a]+BB[b2]) * HH * cxf * lgx
         + 0.5f*(RHO[a]+RHO[b2]) * (0.5f*(PP[a]+PP[b2])) * cxf * gux
         + 0.5f*(g_RB[a]+g_RB[b2]) * (0.5f*(BNX[a]+BNX[b2])) * cxf * gux;
}

__device__ __forceinline__ float fluxY(const float* C, const float* U, const float* LAP,
                                       const float* RHO, const float* QQ, const float* BB,
                                       const float* BNY, int a) {
    int b2 = a + 1;
    float ca = C[a], cb = C[b2];
    float cyf = 2.f*ca*cb / (ca + cb + EPSF);
    float guy = (U[b2] - U[a]) * INVH;
    float lgy = (LAP[b2] - LAP[a]) * INVH;
    return 0.5f*(BB[a]+BB[b2]) * HH * cyf * lgy
         + 0.5f*(RHO[a]+RHO[b2]) * (0.5f*(QQ[a]+QQ[b2])) * cyf * guy
         + 0.5f*(g_RB[a]+g_RB[b2]) * (0.5f*(BNY[a]+BNY[b2])) * cyf * guy;
}

__global__ void s2_kernel(const float* __restrict__ coeff, const float* __restrict__ u) {
    int b = blockIdx.y;
    size_t off = (size_t)b * Nc;
    const float* C = coeff + off;
    const float* U = u + off;
    const float* LAP = g_lap + off;
    const float* RHO = g_rho + off;
    const float* PP  = g_P + off;
    const float* QQ  = g_Q + off;
    const float* BB  = g_BB + off;
    const float* BNX = g_BNX + off;
    const float* BNY = g_BNY + off;
    int base = blockIdx.x * CPBs;

    for (int t = threadIdx.x; t < CPBs; t += TPBs) {
        int idx = base + t;
        int i = idx >> 9;
        int j = idx & (Sc - 1);
        float rhs = 0.f;
        if (i > 0 && i < Sc-1 && j > 0 && j < Sc-1) {
            float fxN = fluxX(C, U, LAP, RHO, PP, BB, BNX, idx);
            float fxS = fluxX(C, U, LAP, RHO, PP, BB, BNX, idx - Sc);
            float fyE = fluxY(C, U, LAP, RHO, QQ, BB, BNY, idx);
            float fyW = fluxY(C, U, LAP, RHO, QQ, BB, BNY, idx - 1);
            rhs = (fxN - fxS) * INVH + (fyE - fyW) * INVH;
        }
        g_r[off+idx] = rhs;
    }
}

__global__ void zc_kernel() {
    if (threadIdx.x < Bc) { g_cnt[threadIdx.x] = 0u; g_pub[threadIdx.x] = 0ull; }
}

// =====================================================================
// barrier + deterministic cross-block reduction with single-u64 broadcast
// =====================================================================
__device__ __forceinline__ float sync_reduce(float v, float* sRed, int b, int rblk, unsigned ev) {
#pragma unroll
    for (int o = 16; o > 0; o >>= 1) v += __shfl_down_sync(0xffffffffu, v, o);
    if ((threadIdx.x & 31) == 0) sRed[threadIdx.x >> 5] = v;
    __syncthreads();
    if (threadIdx.x == 0) {
        float s = 0.f;
#pragma unroll
        for (int w = 0; w < 16; w++) s += sRed[w];
        g_part[b*BPB + rblk] = s;
        unsigned old;
        asm volatile("atom.acq_rel.gpu.global.add.u32 %0, [%1], %2;"
                     : "=r"(old) : "l"(&g_cnt[b]), "r"(1u) : "memory");
        if (old == ev*BPB - 1u) {
            const float* pp = &g_part[b*BPB];
            float tsum = 0.f;
#pragma unroll
            for (int i = 0; i < BPB; i++) tsum += pp[i];
            unsigned long long pk = ((unsigned long long)ev << 32) |
                                    (unsigned long long)__float_as_uint(tsum);
            asm volatile("st.release.gpu.global.b64 [%0], %1;"
                         :: "l"(&g_pub[b]), "l"(pk) : "memory");
            sRed[0] = tsum;
        } else {
            unsigned long long pk;
            do {
                asm volatile("ld.acquire.gpu.global.b64 %0, [%1];"
                             : "=l"(pk) : "l"(&g_pub[b]) : "memory");
            } while ((unsigned)(pk >> 32) != ev);
            sRed[0] = __uint_as_float((unsigned)pk);
        }
    }
    __syncthreads();
    float r = sRed[0];
    __syncthreads();
    return r;
}

#define SMEM_FLOATS (16*PT + 16*PT + 16*PT + 32)
#define SMEM_BYTES (SMEM_FLOATS * 4)

__global__ void __launch_bounds__(PT, 2)
cg_kernel(const float* __restrict__ u, float* __restrict__ out) {
    extern __shared__ float sm[];
    float* sP   = sm;                 // p, 16 own rows (horizontal neighbor access)
    float* sR   = sm + 16*PT;
    float* sAP  = sR + 16*PT;
    float* sRed = sAP + 16*PT;

    const int t = threadIdx.x;
    const int blk = blockIdx.x;
    const int b = blk >> 5;
    const int rblk = blk & 31;
    const int R0 = rblk * ROWS;
    const size_t off = (size_t)b * Nc;
    const size_t gb = off + (size_t)R0 * Sc + t;
    const float* __restrict__ CX = g_cxs + (size_t)b*(Sc-1)*Sc;
    const float* __restrict__ CY = g_cys + (size_t)b*Sc*(Sc-1);
    unsigned ev = 0;

    const bool interiorT = (t > 0 && t < Sc-1);
    float x[ROWS], pc[ROWS];
    float pHT = 0.f, pHB = 0.f;   // p_old at halo rows R0-1 and R0+16

    // ---- init: r from s2 into smem; p_old = 0; rr0 partial ----
    float acc = 0.f;
#pragma unroll
    for (int k = 0; k < ROWS; k++) {
        float rv = g_r[gb + k*Sc];
        sR[k*PT + t] = rv;
        pc[k] = 0.f;
        x[k] = 0.f;
        acc += rv * rv;
    }
    ev++;
    float rr = sync_reduce(acc, sRed, b, rblk, ev);   // also publishes g_r visibility
    float rr_old = rr;

    for (int it = 0; it < ITERS; it++) {
        float beta = (it == 0) ? 0.f : rr / fmaxf(rr_old, EPSF);

        // ---- phase A: p = r + beta*p_old (incl. halo), ap = A(p), pAp ----
        float rHT = (rblk > 0)     ? g_r[gb - Sc]      : 0.f;
        float rHB = (rblk < BPB-1) ? g_r[gb + ROWS*Sc] : 0.f;
        pHT = rHT + beta * pHT;
        pHB = rHB + beta * pHB;
#pragma unroll
        for (int k = 0; k < ROWS; k++) {
            float pv = sR[k*PT + t] + beta * pc[k];
            pc[k] = pv;
            sP[k*PT + t] = pv;
        }
        __syncthreads();

        float pAcc = 0.f;
        // vertical-face coefficient carried across rows: cxs[k] = cxn[k-1]
        float cxn_prev = CX[(size_t)(R0 > 0 ? R0-1 : 0)*Sc + t];
        int tcy = (t < Sc-1) ? t : Sc-2;
#pragma unroll
        for (int k = 0; k < ROWS; k++) {
            int i = R0 + k;
            int icx = (i < Sc-1) ? i : Sc-2;
            float cxn = CX[(size_t)icx*Sc + t];
            float cye = CY[(size_t)i*(Sc-1) + tcy];
            float cyw = __shfl_up_sync(0xffffffffu, cye, 1);
            if ((t & 31) == 0) cyw = CY[(size_t)i*(Sc-1) + ((t > 0) ? t-1 : 0)];

            float ap = 0.f;
            if (i > 0 && i < Sc-1 && interiorT) {
                float pcc = pc[k];
                float pd = (k == 0)      ? pHT : pc[k-1];
                float pu = (k == ROWS-1) ? pHB : pc[k+1];
                float pe = sP[k*PT + t + 1];
                float pw = sP[k*PT + t - 1];
                ap = cxn*(pcc-pu) + cxn_prev*(pcc-pd) + cye*(pcc-pe) + cyw*(pcc-pw);
                pAcc += pcc * ap;
            }
            sAP[k*PT + t] = ap;
            cxn_prev = cxn;
        }
        ev++;
        float pap = sync_reduce(pAcc, sRed, b, rblk, ev);
        float alpha = rr / fmaxf(pap, EPSF);

        // ---- phase B: x += alpha p; r -= alpha ap; rr partial; edge r -> global ----
        if (it < ITERS-1) {
            float racc = 0.f;
#pragma unroll
            for (int k = 0; k < ROWS; k++) {
                x[k] += alpha * pc[k];
                float rv = sR[k*PT + t] - alpha * sAP[k*PT + t];
                sR[k*PT + t] = rv;
                racc += rv * rv;
                if (k == 0 || k == ROWS-1) g_r[gb + k*Sc] = rv;
            }
            ev++;
            rr_old = rr;
            rr = sync_reduce(racc, sRed, b, rblk, ev);
        } else {
#pragma unroll
            for (int k = 0; k < ROWS; k++) x[k] += alpha * pc[k];
        }
    }

    // ---- output: out = zb(u + x) ----
#pragma unroll
    for (int k = 0; k < ROWS; k++) {
        int i = R0 + k;
        size_t gi = gb + k*Sc;
        float v = 0.f;
        if (i > 0 && i < Sc-1 && interiorT) v = u[gi] + x[k];
        out[gi] = v;
    }
}

extern "C" void kernel_launch(void* const* d_in, const int* in_sizes, int n_in,
                              void* d_out, int out_size) {
    const float* coeff = (const float*)d_in[0];
    const float* u     = (const float*)d_in[1];
    const float* beta  = (const float*)d_in[2];
    float* out = (float*)d_out;

    cudaFuncSetAttribute(cg_kernel, cudaFuncAttributeMaxDynamicSharedMemorySize, SMEM_BYTES);

    zc_kernel<<<1, 32>>>();
    dim3 grid(NBs, Bc), blkd(TPBs);
    s1_kernel<<<grid, blkd>>>(coeff, u, beta);
    s2_kernel<<<grid, blkd>>>(coeff, u);
    cg_kernel<<<PB, PT, SMEM_BYTES>>>(u, out);
}